// round 13
// baseline (speedup 1.0000x reference)
#include <cuda_runtime.h>
#include <cuda_fp16.h>
#include <cstdint>

#define N_NODES 100000
#define N_EDGES 3200000
#define N_RELS  8
#define F_DIM   64

#define SCAN_BLK 1024
#define SCAN_NBLK ((N_NODES + SCAN_BLK - 1) / SCAN_BLK)   // 98

#define EBLOCKS ((N_EDGES + 255) / 256)                   // 12500
#define WCONV_BLOCKS ((N_RELS * 64 * 64 + 255) / 256)     // 128
#define XW_BLOCKS ((N_NODES + 63) / 64)                   // 1563

// fp16 per-relation transformed features: 102.4 MB
__device__ __half g_XWh[(size_t)N_RELS * N_NODES * F_DIM];
// fp16 transposed weights: g_Wht[r][n][k]
__device__ __half g_Wht[N_RELS * F_DIM * F_DIM];
// CSR-by-dst build
__device__ int g_count[N_NODES];
__device__ int g_tmp[N_NODES];
__device__ int g_start[N_NODES];
__device__ int g_rank[N_EDGES];       // edge rank within its dst (from hist)
__device__ int g_blocktot[SCAN_NBLK];
__device__ int g_blockoff[SCAN_NBLK];
// packed edge records grouped by dst: lo32 = src | (rel<<17), hi32 = bits(A)
__device__ __align__(16) unsigned long long g_recs[N_EDGES];

// ---------------------------------------------------------------------------
// Fused: histogram (stores rank) + W pre-convert/transpose
// ---------------------------------------------------------------------------
__global__ __launch_bounds__(256) void hist_wconv_kernel(const int* __restrict__ dst,
                                                         const float* __restrict__ W) {
    int bx = blockIdx.x;
    if (bx < EBLOCKS) {
        int e = bx * 256 + threadIdx.x;
        if (e < N_EDGES) {
            int p = atomicAdd(&g_count[dst[e]], 1);
            g_rank[e] = p;
        }
    } else {
        int i = (bx - EBLOCKS) * 256 + threadIdx.x;
        if (i < N_RELS * 64 * 64) {
            int r = i >> 12;
            int n = (i >> 6) & 63;
            int k = i & 63;
            g_Wht[i] = __float2half_rn(W[r * 4096 + k * 64 + n]);
        }
    }
}

// ---------------------------------------------------------------------------
// Scan (3 kernels)
// ---------------------------------------------------------------------------
__global__ __launch_bounds__(SCAN_BLK) void scan1_kernel() {
    __shared__ int s[SCAN_BLK];
    int t = threadIdx.x;
    int i = blockIdx.x * SCAN_BLK + t;
    int v = (i < N_NODES) ? g_count[i] : 0;
    s[t] = v;
    __syncthreads();
    for (int off = 1; off < SCAN_BLK; off <<= 1) {
        int add = (t >= off) ? s[t - off] : 0;
        __syncthreads();
        s[t] += add;
        __syncthreads();
    }
    if (i < N_NODES) g_tmp[i] = s[t];
    if (t == SCAN_BLK - 1) g_blocktot[blockIdx.x] = s[t];
}

__global__ __launch_bounds__(128) void scan2_kernel() {
    __shared__ int s[128];
    int t = threadIdx.x;
    s[t] = (t < SCAN_NBLK) ? g_blocktot[t] : 0;
    __syncthreads();
    for (int off = 1; off < 128; off <<= 1) {
        int add = (t >= off) ? s[t - off] : 0;
        __syncthreads();
        s[t] += add;
        __syncthreads();
    }
    if (t < SCAN_NBLK) g_blockoff[t] = s[t] - g_blocktot[t];
}

__global__ __launch_bounds__(SCAN_BLK) void scan3_kernel() {
    int i = blockIdx.x * SCAN_BLK + threadIdx.x;
    if (i < N_NODES) {
        g_start[i] = g_tmp[i] - g_count[i] + g_blockoff[blockIdx.x];
    }
}

// ---------------------------------------------------------------------------
// Fused: atomic-free record scatter + XW GEMM (co-resident overlap)
// ---------------------------------------------------------------------------
__global__ __launch_bounds__(256) void scatter_xw_kernel(const float* __restrict__ A,
                                                         const int* __restrict__ src,
                                                         const int* __restrict__ dst,
                                                         const int* __restrict__ etype,
                                                         const float* __restrict__ X,
                                                         __half* __restrict__ XWh) {
    __shared__ __half Xh[64][72];
    __shared__ __half Wt[64][72];

    int bx = blockIdx.x;
    if (bx >= XW_BLOCKS) {
        // ---- scatter path (no atomics) ----
        int e = (bx - XW_BLOCKS) * 256 + threadIdx.x;
        if (e >= N_EDGES) return;
        int d = dst[e];
        int p = g_start[d] + g_rank[e];
        unsigned key = (unsigned)src[e] | ((unsigned)etype[e] << 17);
        unsigned long long rec = (unsigned long long)key |
                                 ((unsigned long long)__float_as_uint(A[e]) << 32);
        g_recs[p] = rec;
        return;
    }

    // ---- xw path ----
    const int n0blk = bx * 64;

    for (int i = threadIdx.x; i < 64 * 32; i += 256) {
        int row = i >> 5, cp = i & 31;
        int n = n0blk + row;
        float2 v = (n < N_NODES)
            ? *reinterpret_cast<const float2*>(X + (size_t)n * 64 + cp * 2)
            : make_float2(0.0f, 0.0f);
        *reinterpret_cast<__half2*>(&Xh[row][cp * 2]) = __floats2half2_rn(v.x, v.y);
    }

    const int warp = threadIdx.x >> 5;
    const int lane = threadIdx.x & 31;
    const int g = lane >> 2;
    const int t = lane & 3;
    const int r0 = (warp & 3) * 16;
    const int ch = (warp >> 2) * 32;

    for (int r = 0; r < N_RELS; r++) {
        __syncthreads();
        for (int i = threadIdx.x; i < 64 * 32; i += 256) {
            int n = i >> 5, kp = i & 31;
            *reinterpret_cast<__half2*>(&Wt[n][kp * 2]) =
                *reinterpret_cast<const __half2*>(&g_Wht[r * 4096 + n * 64 + kp * 2]);
        }
        __syncthreads();

        float acc[4][4];
#pragma unroll
        for (int j = 0; j < 4; j++)
#pragma unroll
            for (int c = 0; c < 4; c++) acc[j][c] = 0.0f;

#pragma unroll
        for (int kk = 0; kk < 4; kk++) {
            const int k0 = kk * 16;
            uint32_t a0 = *reinterpret_cast<const uint32_t*>(&Xh[r0 + g    ][k0 + 2 * t    ]);
            uint32_t a1 = *reinterpret_cast<const uint32_t*>(&Xh[r0 + g + 8][k0 + 2 * t    ]);
            uint32_t a2 = *reinterpret_cast<const uint32_t*>(&Xh[r0 + g    ][k0 + 2 * t + 8]);
            uint32_t a3 = *reinterpret_cast<const uint32_t*>(&Xh[r0 + g + 8][k0 + 2 * t + 8]);
#pragma unroll
            for (int j = 0; j < 4; j++) {
                const int n0 = ch + j * 8;
                uint32_t b0 = *reinterpret_cast<const uint32_t*>(&Wt[n0 + g][k0 + 2 * t    ]);
                uint32_t b1 = *reinterpret_cast<const uint32_t*>(&Wt[n0 + g][k0 + 2 * t + 8]);
                asm volatile(
                    "mma.sync.aligned.m16n8k16.row.col.f32.f16.f16.f32 "
                    "{%0,%1,%2,%3}, {%4,%5,%6,%7}, {%8,%9}, {%0,%1,%2,%3};"
                    : "+f"(acc[j][0]), "+f"(acc[j][1]), "+f"(acc[j][2]), "+f"(acc[j][3])
                    : "r"(a0), "r"(a1), "r"(a2), "r"(a3), "r"(b0), "r"(b1));
            }
        }

        __half* base = XWh + (size_t)r * N_NODES * 64;
#pragma unroll
        for (int j = 0; j < 4; j++) {
            const int col = ch + j * 8 + 2 * t;
            const int row_a = n0blk + r0 + g;
            const int row_b = row_a + 8;
            __half2 lo = __floats2half2_rn(acc[j][0], acc[j][1]);
            __half2 hi = __floats2half2_rn(acc[j][2], acc[j][3]);
            if (row_a < N_NODES)
                *reinterpret_cast<__half2*>(base + (size_t)row_a * 64 + col) = lo;
            if (row_b < N_NODES)
                *reinterpret_cast<__half2*>(base + (size_t)row_b * 64 + col) = hi;
        }
    }
}

// ---------------------------------------------------------------------------
// Gather: warp-per-node; lane L serves edge base+(L>>3), cols 8*(L&7)..+8.
// One LDG.128 covers 4 edges' rows. Hot loop branch-free; shuffles only at
// node end. 6 warp-LDGs per 8 edges.
// ---------------------------------------------------------------------------
__global__ __launch_bounds__(256) void gather_kernel(const __half* __restrict__ XWh,
                                                     float* __restrict__ Y) {
    const int node = blockIdx.x * 8 + (threadIdx.x >> 5);
    if (node >= N_NODES) return;
    const int lane = threadIdx.x & 31;
    const int sub  = lane >> 3;          // which edge in group of 4
    const int col8 = (lane & 7) * 8;     // starting column (halves)

    const int s = g_start[node];
    const int end = s + g_count[node];

    float acc[8];
#pragma unroll
    for (int j = 0; j < 8; j++) acc[j] = 0.0f;

    int i = s;
    // Peel one edge if start is odd (align uint4 record reads to 16B)
    if ((i & 1) && i < end) {
        if (sub == 0) {   // lanes 0..7 cover all 64 cols
            unsigned long long r0 = g_recs[i];
            unsigned k0 = (unsigned)r0;
            float a0 = __uint_as_float((unsigned)(r0 >> 32));
            size_t row = (size_t)(k0 >> 17) * N_NODES + (k0 & 0x1FFFF);
            uint4 h = *reinterpret_cast<const uint4*>(XWh + row * 64 + col8);
            const __half2* p = reinterpret_cast<const __half2*>(&h);
#pragma unroll
            for (int j = 0; j < 4; j++) {
                float2 f = __half22float2(p[j]);
                acc[2 * j]     = fmaf(f.x, a0, acc[2 * j]);
                acc[2 * j + 1] = fmaf(f.y, a0, acc[2 * j + 1]);
            }
        }
        i++;
    }

    // Hot loop: 8 edges per iteration (2 groups of 4), branch-free
    for (; i + 8 <= end; i += 8) {
        uint4 ra0 = *reinterpret_cast<const uint4*>(g_recs + i);
        uint4 rb0 = *reinterpret_cast<const uint4*>(g_recs + i + 2);
        uint4 ra1 = *reinterpret_cast<const uint4*>(g_recs + i + 4);
        uint4 rb1 = *reinterpret_cast<const uint4*>(g_recs + i + 6);

        unsigned k0 = sub == 0 ? ra0.x : sub == 1 ? ra0.z : sub == 2 ? rb0.x : rb0.z;
        float    a0 = __uint_as_float(sub == 0 ? ra0.y : sub == 1 ? ra0.w
                                    : sub == 2 ? rb0.y : rb0.w);
        unsigned k1 = sub == 0 ? ra1.x : sub == 1 ? ra1.z : sub == 2 ? rb1.x : rb1.z;
        float    a1 = __uint_as_float(sub == 0 ? ra1.y : sub == 1 ? ra1.w
                                    : sub == 2 ? rb1.y : rb1.w);

        size_t row0 = (size_t)(k0 >> 17) * N_NODES + (k0 & 0x1FFFF);
        size_t row1 = (size_t)(k1 >> 17) * N_NODES + (k1 & 0x1FFFF);
        uint4 h0 = *reinterpret_cast<const uint4*>(XWh + row0 * 64 + col8);
        uint4 h1 = *reinterpret_cast<const uint4*>(XWh + row1 * 64 + col8);

        const __half2* p0 = reinterpret_cast<const __half2*>(&h0);
        const __half2* p1 = reinterpret_cast<const __half2*>(&h1);
#pragma unroll
        for (int j = 0; j < 4; j++) {
            float2 f0 = __half22float2(p0[j]);
            float2 f1 = __half22float2(p1[j]);
            acc[2 * j]     = fmaf(f0.x, a0, acc[2 * j]);
            acc[2 * j + 1] = fmaf(f0.y, a0, acc[2 * j + 1]);
            acc[2 * j]     = fmaf(f1.x, a1, acc[2 * j]);
            acc[2 * j + 1] = fmaf(f1.y, a1, acc[2 * j + 1]);
        }
    }

    // Remainder: masked groups of up to 4 edges
    for (; i < end; i += 4) {
        int m = end - i;
        bool v = sub < m;
        unsigned long long r = v ? g_recs[i + sub] : 0ULL;
        unsigned k = (unsigned)r;
        float aa = __uint_as_float((unsigned)(r >> 32));
        size_t row = (size_t)(k >> 17) * N_NODES + (k & 0x1FFFF);
        uint4 h = make_uint4(0, 0, 0, 0);
        if (v) h = *reinterpret_cast<const uint4*>(XWh + row * 64 + col8);
        if (!v) aa = 0.0f;
        const __half2* p = reinterpret_cast<const __half2*>(&h);
#pragma unroll
        for (int j = 0; j < 4; j++) {
            float2 f = __half22float2(p[j]);
            acc[2 * j]     = fmaf(f.x, aa, acc[2 * j]);
            acc[2 * j + 1] = fmaf(f.y, aa, acc[2 * j + 1]);
        }
    }

    // Combine the 4 sub-group partials (lanes L, L^8, L^16, L^24)
#pragma unroll
    for (int j = 0; j < 8; j++) {
        acc[j] += __shfl_xor_sync(0xffffffffu, acc[j], 8);
        acc[j] += __shfl_xor_sync(0xffffffffu, acc[j], 16);
    }

    if (lane < 8) {
        float4* out = reinterpret_cast<float4*>(Y + (size_t)node * 64 + col8);
        out[0] = make_float4(acc[0], acc[1], acc[2], acc[3]);
        out[1] = make_float4(acc[4], acc[5], acc[6], acc[7]);
    }
}

// ---------------------------------------------------------------------------
extern "C" void kernel_launch(void* const* d_in, const int* in_sizes, int n_in,
                              void* d_out, int out_size) {
    const float* X     = (const float*)d_in[0];
    const float* W     = (const float*)d_in[1];
    const float* A     = (const float*)d_in[2];
    const int*   src   = (const int*)d_in[3];
    const int*   dst   = (const int*)d_in[4];
    const int*   etype = (const int*)d_in[5];
    float* Y = (float*)d_out;

    __half* XWh = nullptr;
    cudaGetSymbolAddress((void**)&XWh, g_XWh);
    void* countp = nullptr;
    cudaGetSymbolAddress(&countp, g_count);

    cudaMemsetAsync(countp, 0, N_NODES * sizeof(int), 0);

    hist_wconv_kernel<<<EBLOCKS + WCONV_BLOCKS, 256>>>(dst, W);
    scan1_kernel<<<SCAN_NBLK, SCAN_BLK>>>();
    scan2_kernel<<<1, 128>>>();
    scan3_kernel<<<SCAN_NBLK, SCAN_BLK>>>();

    // atomic-free scatter + XW GEMM co-resident
    scatter_xw_kernel<<<XW_BLOCKS + EBLOCKS, 256>>>(A, src, dst, etype, X, XWh);

    // warp-per-node gather (writes every Y element; no memset needed)
    gather_kernel<<<(N_NODES + 7) / 8, 256>>>(XWh, Y);
}